// round 1
// baseline (speedup 1.0000x reference)
#include <cuda_runtime.h>
#include <math.h>
#include <stdint.h>

// ---------------- problem constants ----------------
constexpr int T_    = 64;
constexpr int B_    = 32;
constexpr int D_    = 1024;
constexpr int L_    = 2;
constexpr int MEM_  = 35;
constexpr int NTOK_ = 32000;
constexpr int DK_   = 512;     // D / HEADS
constexpr int MB_   = MEM_ * B_;   // 1120
constexpr int BD_   = B_ * D_;     // 32768
constexpr float EPS_   = 1e-6f;
constexpr float SCALE_ = 0.04419417382415922f;  // 1/sqrt(512)

// AV split-K groups
constexpr int GAV_   = 10;
constexpr int MTILE_ = 112;   // 1120 / 10

// output layout (floats): decoded, h, c, H, C
constexpr long long OFF_DEC = 0;
constexpr long long SZ_DEC  = (long long)T_ * B_ * NTOK_;          // 65,536,000
constexpr long long OFF_H   = OFF_DEC + SZ_DEC;
constexpr long long SZ_HC   = (long long)L_ * B_ * D_;             // 65,536
constexpr long long OFF_C   = OFF_H + SZ_HC;
constexpr long long OFF_HM  = OFF_C + SZ_HC;
constexpr long long SZ_HM   = (long long)L_ * MEM_ * B_ * D_;      // 2,293,760
constexpr long long OFF_CM  = OFF_HM + SZ_HM;
constexpr long long TOTAL_OUT = OFF_CM + SZ_HM;                    // 70,254,592

// ---------------- device scratch (static; no allocation) ----------------
__device__ float g_e[BD_];
__device__ float g_q[BD_];
__device__ float g_Kc[MEM_ * BD_];          // key cache rows [MEM*B][D]
__device__ float g_Vc[MEM_ * BD_];
__device__ float g_scores[2 * B_ * MB_];    // [h*B+b][1120]
__device__ float g_attp[GAV_ * BD_];        // AV partials [g][B][D]
__device__ float g_hsum[L_ * BD_];          // h_att + h_carry per layer
__device__ float g_h[L_ * BD_];             // carry h
__device__ float g_c[L_ * BD_];             // carry c
__device__ float g_xs[(long long)T_ * BD_]; // LSTM top-layer outputs (decoder input)

__device__ __forceinline__ float sigm(float x) { return 1.f / (1.f + expf(-x)); }
__device__ __forceinline__ float dot4(float4 a, float4 b) {
    return a.x*b.x + a.y*b.y + a.z*b.z + a.w*b.w;
}

// ---------------- init carry state ----------------
__global__ void k_init_state(const float* __restrict__ h0, const float* __restrict__ c0) {
    int i = blockIdx.x * blockDim.x + threadIdx.x;
    if (i < L_ * BD_) { g_h[i] = h0[i]; g_c[i] = c0[i]; }
}

// ---------------- tiled SGEMM: C[M,N] = A[M,K] @ W[N,K]^T + bias ----------------
// asel: 1 -> A = g_xs ; csel: 0 -> g_Kc, 1 -> g_Vc, 2 -> Cext
__global__ __launch_bounds__(256, 2)
void k_gemm(const float* __restrict__ Aext, const float* __restrict__ W,
            const float* __restrict__ bias, float* Cext,
            int M, int N, int K, int asel, int csel) {
    const float* A = (asel == 1) ? (const float*)g_xs : Aext;
    float* C = (csel == 0) ? g_Kc : (csel == 1) ? g_Vc : Cext;

    __shared__ __align__(16) float As[8][128];
    __shared__ __align__(16) float Bs[8][128];

    int m0 = blockIdx.x * 128;
    int n0 = blockIdx.y * 128;
    int tid = threadIdx.x;
    int tr = tid / 16, tc = tid % 16;
    int lr = tid / 2;            // 0..127
    int lk = (tid % 2) * 4;      // 0 or 4

    float acc[8][8];
#pragma unroll
    for (int i = 0; i < 8; i++)
#pragma unroll
        for (int j = 0; j < 8; j++) acc[i][j] = 0.f;

    for (int k0 = 0; k0 < K; k0 += 8) {
        float4 av = make_float4(0,0,0,0), bv = make_float4(0,0,0,0);
        if (m0 + lr < M) av = *(const float4*)&A[(size_t)(m0 + lr) * K + k0 + lk];
        if (n0 + lr < N) bv = *(const float4*)&W[(size_t)(n0 + lr) * K + k0 + lk];
        __syncthreads();
        As[lk+0][lr] = av.x; As[lk+1][lr] = av.y; As[lk+2][lr] = av.z; As[lk+3][lr] = av.w;
        Bs[lk+0][lr] = bv.x; Bs[lk+1][lr] = bv.y; Bs[lk+2][lr] = bv.z; Bs[lk+3][lr] = bv.w;
        __syncthreads();
#pragma unroll
        for (int k = 0; k < 8; k++) {
            float af[8], bf[8];
            *(float4*)&af[0] = *(const float4*)&As[k][tr * 4];
            *(float4*)&af[4] = *(const float4*)&As[k][64 + tr * 4];
            *(float4*)&bf[0] = *(const float4*)&Bs[k][tc * 4];
            *(float4*)&bf[4] = *(const float4*)&Bs[k][64 + tc * 4];
#pragma unroll
            for (int i = 0; i < 8; i++)
#pragma unroll
                for (int j = 0; j < 8; j++) acc[i][j] += af[i] * bf[j];
        }
    }
    int rb[2] = { m0 + tr * 4, m0 + 64 + tr * 4 };
    int cb[2] = { n0 + tc * 4, n0 + 64 + tc * 4 };
#pragma unroll
    for (int ih = 0; ih < 2; ih++)
#pragma unroll
        for (int i = 0; i < 4; i++) {
            int m = rb[ih] + i;
            if (m >= M) continue;
#pragma unroll
            for (int jh = 0; jh < 2; jh++)
#pragma unroll
                for (int j = 0; j < 4; j++) {
                    int n = cb[jh] + j;
                    if (n < N) C[(size_t)m * N + n] = acc[ih*4+i][jh*4+j] + bias[n];
                }
        }
}

// ---------------- embed + LayerNorm + Q projection ----------------
// grid (B, 4), 256 threads
__global__ void k_embed_ln_q(const int* __restrict__ tokens, const float* __restrict__ emb,
                             const float* __restrict__ lng, const float* __restrict__ lnb,
                             const float* __restrict__ Wq, const float* __restrict__ bq, int t) {
    __shared__ __align__(16) float esh[D_];
    __shared__ __align__(16) float nsh[D_];
    __shared__ float rs[8], rs2[8];
    int b = blockIdx.x, tid = threadIdx.x;
    int tok = tokens[t * B_ + b];
    const float* erow = emb + (size_t)tok * D_;
    float s = 0.f, s2 = 0.f;
    for (int i = tid; i < D_; i += 256) { float v = erow[i]; esh[i] = v; s += v; s2 += v*v; }
#pragma unroll
    for (int o = 16; o; o >>= 1) { s += __shfl_xor_sync(~0u, s, o); s2 += __shfl_xor_sync(~0u, s2, o); }
    if ((tid & 31) == 0) { rs[tid >> 5] = s; rs2[tid >> 5] = s2; }
    __syncthreads();
    if (tid == 0) {
        float a = 0.f, c = 0.f;
        for (int w = 0; w < 8; w++) { a += rs[w]; c += rs2[w]; }
        rs[0] = a; rs2[0] = c;
    }
    __syncthreads();
    float mu  = rs[0] / D_;
    float var = (rs2[0] - (float)D_ * mu * mu) / (float)(D_ - 1);
    float inv = 1.f / (sqrtf(fmaxf(var, 0.f)) + EPS_);
    for (int i = tid; i < D_; i += 256) nsh[i] = lng[i] * (esh[i] - mu) * inv + lnb[i];
    __syncthreads();
    if (blockIdx.y == 0)
        for (int i = tid; i < D_; i += 256) g_e[b * D_ + i] = esh[i];
    int o = blockIdx.y * 256 + tid;
    const float4* n4 = (const float4*)nsh;
    const float4* w4 = (const float4*)(Wq + (size_t)o * D_);
    float acc = 0.f;
#pragma unroll 4
    for (int i = 0; i < D_/4; i++) acc += dot4(n4[i], w4[i]);
    g_q[b * D_ + o] = acc + bq[o];
}

// ---------------- attention scores ---------------- grid (64, 5), 256 threads
__global__ void k_scores() {
    __shared__ __align__(16) float qsh[DK_];
    int hb = blockIdx.x, h = hb >> 5, b = hb & 31, tid = threadIdx.x;
    for (int i = tid; i < DK_; i += 256) qsh[i] = g_q[b * D_ + h * DK_ + i];
    __syncthreads();
    int m = blockIdx.y * 256 + tid;
    if (m < MB_) {
        const float4* k4 = (const float4*)(g_Kc + (size_t)m * D_ + h * DK_);
        const float4* q4 = (const float4*)qsh;
        float acc = 0.f;
#pragma unroll 4
        for (int i = 0; i < DK_/4; i++) acc += dot4(q4[i], k4[i]);
        g_scores[(size_t)hb * MB_ + m] = acc * SCALE_;
    }
}

// ---------------- softmax over m ---------------- grid 64, 256 threads
__global__ void k_softmax() {
    int hb = blockIdx.x, tid = threadIdx.x;
    float* row = g_scores + (size_t)hb * MB_;
    __shared__ float red[8];
    float mx = -1e30f;
    for (int i = tid; i < MB_; i += 256) mx = fmaxf(mx, row[i]);
#pragma unroll
    for (int o = 16; o; o >>= 1) mx = fmaxf(mx, __shfl_xor_sync(~0u, mx, o));
    if ((tid & 31) == 0) red[tid >> 5] = mx;
    __syncthreads();
    if (tid == 0) { float v = red[0]; for (int w = 1; w < 8; w++) v = fmaxf(v, red[w]); red[0] = v; }
    __syncthreads();
    mx = red[0];
    __syncthreads();
    float s = 0.f;
    for (int i = tid; i < MB_; i += 256) { float e = expf(row[i] - mx); row[i] = e; s += e; }
#pragma unroll
    for (int o = 16; o; o >>= 1) s += __shfl_xor_sync(~0u, s, o);
    if ((tid & 31) == 0) red[tid >> 5] = s;
    __syncthreads();
    if (tid == 0) { float v = 0.f; for (int w = 0; w < 8; w++) v += red[w]; red[0] = v; }
    __syncthreads();
    float inv = 1.f / red[0];
    for (int i = tid; i < MB_; i += 256) row[i] *= inv;
}

// ---------------- AV: att partials, register-blocked over b ----------------
// grid (8 d-chunks, GAV_ m-groups), 128 threads
__global__ void k_av() {
    __shared__ __align__(16) float sw[MTILE_][B_];
    int tid = threadIdx.x;
    int d = blockIdx.x * 128 + tid;
    int h = d >> 9;
    int m0 = blockIdx.y * MTILE_;
    for (int idx = tid; idx < MTILE_ * B_; idx += 128) {
        int mm = idx >> 5, bb = idx & 31;
        sw[mm][bb] = g_scores[(size_t)(h * B_ + bb) * MB_ + m0 + mm];
    }
    __syncthreads();
    float acc[B_];
#pragma unroll
    for (int i = 0; i < B_; i++) acc[i] = 0.f;
#pragma unroll 4
    for (int mm = 0; mm < MTILE_; mm++) {
        float v = g_Vc[(size_t)(m0 + mm) * D_ + d];
        const float4* w4 = (const float4*)sw[mm];
#pragma unroll
        for (int q = 0; q < 8; q++) {
            float4 w = w4[q];
            acc[q*4+0] += w.x * v; acc[q*4+1] += w.y * v;
            acc[q*4+2] += w.z * v; acc[q*4+3] += w.w * v;
        }
    }
    float* dst = g_attp + (size_t)blockIdx.y * BD_;
#pragma unroll
    for (int bb = 0; bb < B_; bb++) dst[bb * D_ + d] = acc[bb];
}

// ---------------- O-proj + residuals + hsum ---------------- grid (B,4), 256 threads
__global__ void k_oproj(const float* __restrict__ Wo, const float* __restrict__ bo) {
    __shared__ __align__(16) float attsh[D_];
    int b = blockIdx.x, tid = threadIdx.x;
    for (int i = tid; i < D_; i += 256) {
        float s = 0.f;
#pragma unroll
        for (int g = 0; g < GAV_; g++) s += g_attp[(size_t)g * BD_ + b * D_ + i];
        attsh[i] = s;
    }
    __syncthreads();
    int o = blockIdx.y * 256 + tid;
    const float4* a4 = (const float4*)attsh;
    const float4* w4 = (const float4*)(Wo + (size_t)o * D_);
    float acc = 0.f;
#pragma unroll 4
    for (int i = 0; i < D_/4; i++) acc += dot4(a4[i], w4[i]);
    float h_att = acc + bo[o] + g_e[b * D_ + o];
    g_hsum[b * D_ + o]       = h_att + g_h[b * D_ + o];
    g_hsum[BD_ + b * D_ + o] = h_att + g_h[BD_ + b * D_ + o];
}

// ---------------- LSTM layer ---------------- grid (B, 8), 128 threads
__global__ void k_lstm(const float* __restrict__ Wih, const float* __restrict__ bih,
                       const float* __restrict__ Whh, const float* __restrict__ bhh,
                       int l, int t, float* __restrict__ out, int full) {
    __shared__ __align__(16) float xsh[D_];
    __shared__ __align__(16) float hsh[D_];
    int b = blockIdx.x, tid = threadIdx.x;
    const float* x = (l == 0) ? g_e : g_h;   // layer1 input = layer0 new h (first BD_)
    for (int i = tid; i < D_; i += 128) {
        xsh[i] = x[b * D_ + i];
        hsh[i] = g_hsum[l * BD_ + b * D_ + i];
    }
    __syncthreads();
    int o = blockIdx.y * 128 + tid;
    size_t base = ((size_t)l * 4 * D_ + o) * D_;
    const float4* wi0 = (const float4*)(Wih + base);
    const float4* wi1 = (const float4*)(Wih + base + (size_t)1 * D_ * D_);
    const float4* wi2 = (const float4*)(Wih + base + (size_t)2 * D_ * D_);
    const float4* wi3 = (const float4*)(Wih + base + (size_t)3 * D_ * D_);
    const float4* wh0 = (const float4*)(Whh + base);
    const float4* wh1 = (const float4*)(Whh + base + (size_t)1 * D_ * D_);
    const float4* wh2 = (const float4*)(Whh + base + (size_t)2 * D_ * D_);
    const float4* wh3 = (const float4*)(Whh + base + (size_t)3 * D_ * D_);
    const float4* x4 = (const float4*)xsh;
    const float4* h4 = (const float4*)hsh;
    float a0 = 0.f, a1 = 0.f, a2 = 0.f, a3 = 0.f;
#pragma unroll 2
    for (int i = 0; i < D_/4; i++) {
        float4 xv = x4[i], hv = h4[i];
        a0 += dot4(xv, wi0[i]); a0 += dot4(hv, wh0[i]);
        a1 += dot4(xv, wi1[i]); a1 += dot4(hv, wh1[i]);
        a2 += dot4(xv, wi2[i]); a2 += dot4(hv, wh2[i]);
        a3 += dot4(xv, wi3[i]); a3 += dot4(hv, wh3[i]);
    }
    int jb = l * 4 * D_;
    float ig = a0 + bih[jb + o]            + bhh[jb + o];
    float fg = a1 + bih[jb + D_ + o]       + bhh[jb + D_ + o];
    float gg = a2 + bih[jb + 2 * D_ + o]   + bhh[jb + 2 * D_ + o];
    float og = a3 + bih[jb + 3 * D_ + o]   + bhh[jb + 3 * D_ + o];
    float c_old = g_c[l * BD_ + b * D_ + o];
    float cn = sigm(fg) * c_old + sigm(ig) * tanhf(gg);
    float hn = sigm(og) * tanhf(cn);
    g_c[l * BD_ + b * D_ + o] = cn;
    g_h[l * BD_ + b * D_ + o] = hn;
    if (l == L_ - 1) g_xs[((size_t)t * B_ + b) * D_ + o] = hn;
    if (full && t >= T_ - MEM_) {
        long long j = t - (T_ - MEM_);
        out[OFF_HM + (((long long)l * MEM_ + j) * B_ + b) * D_ + o] = hn;
        out[OFF_CM + (((long long)l * MEM_ + j) * B_ + b) * D_ + o] = cn;
    }
}

// ---------------- K/V cache update (new row) ---------------- grid (B, 8), 256 threads
__global__ void k_kvupd(const float* __restrict__ Wk, const float* __restrict__ bk,
                        const float* __restrict__ Wv, const float* __restrict__ bv, int t) {
    __shared__ __align__(16) float hsh[D_];
    int b = blockIdx.x, tid = threadIdx.x;
    for (int i = tid; i < D_; i += 256) hsh[i] = g_h[b * D_ + i];   // layer0 new h
    __syncthreads();
    int half = tid >> 7, tt = tid & 127;
    int o = blockIdx.y * 128 + tt;
    const float* W = half ? Wv : Wk;
    const float* bb = half ? bv : bk;
    const float4* h4 = (const float4*)hsh;
    const float4* w4 = (const float4*)(W + (size_t)o * D_);
    float acc = 0.f;
#pragma unroll 4
    for (int i = 0; i < D_/4; i++) acc += dot4(h4[i], w4[i]);
    int slot = t % MEM_;
    float* dst = half ? g_Vc : g_Kc;
    dst[((size_t)slot * B_ + b) * D_ + o] = acc + bb[o];
}

// ---------------- final h,c copy ----------------
__global__ void k_copy_hc(float* __restrict__ out) {
    int i = blockIdx.x * blockDim.x + threadIdx.x;
    if (i < L_ * BD_) { out[OFF_H + i] = g_h[i]; out[OFF_C + i] = g_c[i]; }
}

// ---------------- host launch ----------------
extern "C" void kernel_launch(void* const* d_in, const int* in_sizes, int n_in,
                              void* d_out, int out_size) {
    const int*   tokens = (const int*)  d_in[0];
    const float* emb    = (const float*)d_in[1];
    const float* ln_g   = (const float*)d_in[2];
    const float* ln_b   = (const float*)d_in[3];
    const float* Wq     = (const float*)d_in[4];
    const float* bq     = (const float*)d_in[5];
    const float* Wk     = (const float*)d_in[6];
    const float* bk     = (const float*)d_in[7];
    const float* Wv     = (const float*)d_in[8];
    const float* bv     = (const float*)d_in[9];
    const float* Wo     = (const float*)d_in[10];
    const float* bo     = (const float*)d_in[11];
    const float* W_ih   = (const float*)d_in[12];
    const float* b_ih   = (const float*)d_in[13];
    const float* W_hh   = (const float*)d_in[14];
    const float* b_hh   = (const float*)d_in[15];
    const float* dec_W  = (const float*)d_in[16];
    const float* dec_b  = (const float*)d_in[17];
    const float* h0     = (const float*)d_in[18];
    const float* c0     = (const float*)d_in[19];
    const float* H0     = (const float*)d_in[20];
    float* out = (float*)d_out;
    int full = (out_size >= (int)TOTAL_OUT) ? 1 : 0;

    k_init_state<<<(L_ * BD_ + 255) / 256, 256>>>(h0, c0);

    // K/V cache init from H0[0]  (M=1120, N=1024, K=1024)
    dim3 gi((MB_ + 127) / 128, D_ / 128);
    k_gemm<<<gi, 256>>>(H0, Wk, bk, nullptr, MB_, D_, D_, 0, 0);
    k_gemm<<<gi, 256>>>(H0, Wv, bv, nullptr, MB_, D_, D_, 0, 1);

    for (int t = 0; t < T_; t++) {
        k_embed_ln_q<<<dim3(B_, 4), 256>>>(tokens, emb, ln_g, ln_b, Wq, bq, t);
        k_scores<<<dim3(64, 5), 256>>>();
        k_softmax<<<64, 256>>>();
        k_av<<<dim3(8, GAV_), 128>>>();
        k_oproj<<<dim3(B_, 4), 256>>>(Wo, bo);
        k_lstm<<<dim3(B_, 8), 128>>>(W_ih, b_ih, W_hh, b_hh, 0, t, out, full);
        k_lstm<<<dim3(B_, 8), 128>>>(W_ih, b_ih, W_hh, b_hh, 1, t, out, full);
        k_kvupd<<<dim3(B_, 8), 256>>>(Wk, bk, Wv, bv, t);
    }

    if (full) k_copy_hc<<<(L_ * BD_ + 255) / 256, 256>>>(out);

    // decoder: [T*B, D] @ dec_W^T + dec_b -> decoded at out offset 0
    dim3 gd((T_ * B_) / 128, NTOK_ / 128);
    k_gemm<<<gd, 256>>>(nullptr, dec_W, dec_b, out, T_ * B_, NTOK_, D_, 1, 2);
}

// round 6
// speedup vs baseline: 2.0450x; 2.0450x over previous
#include <cuda_runtime.h>
#include <math.h>
#include <stdint.h>

// ---------------- problem constants ----------------
constexpr int T_    = 64;
constexpr int B_    = 32;
constexpr int D_    = 1024;
constexpr int L_    = 2;
constexpr int MEM_  = 35;
constexpr int NTOK_ = 32000;
constexpr int DK_   = 512;     // D / HEADS
constexpr int MB_   = MEM_ * B_;   // 1120
constexpr int BD_   = B_ * D_;     // 32768
constexpr float EPS_   = 1e-6f;
constexpr float SCALE_ = 0.04419417382415922f;  // 1/sqrt(512)

// AV split groups
constexpr int GAV_   = 10;
constexpr int MTILE_ = 112;   // 1120 / 10

// output layout (floats): decoded, h, c, H, C
constexpr long long OFF_DEC = 0;
constexpr long long SZ_DEC  = (long long)T_ * B_ * NTOK_;          // 65,536,000
constexpr long long OFF_H   = OFF_DEC + SZ_DEC;
constexpr long long SZ_HC   = (long long)L_ * B_ * D_;             // 65,536
constexpr long long OFF_C   = OFF_H + SZ_HC;
constexpr long long OFF_HM  = OFF_C + SZ_HC;
constexpr long long SZ_HM   = (long long)L_ * MEM_ * B_ * D_;      // 2,293,760
constexpr long long OFF_CM  = OFF_HM + SZ_HM;
constexpr long long TOTAL_OUT = OFF_CM + SZ_HM;                    // 70,254,592

// ---------------- device scratch (static; no allocation) ----------------
__device__ float g_e[BD_];
__device__ float g_ln[BD_];
__device__ float g_q[BD_];
__device__ float g_Kc[MEM_ * BD_];          // key cache rows [MEM*B][D]
__device__ float g_Vc[MEM_ * BD_];
__device__ float g_scores[2 * B_ * MB_];    // [(h*B+b)][1120]
__device__ float g_attp[GAV_ * BD_];        // AV partials [g][B][D]
__device__ float g_hsum[L_ * BD_];          // h_att + h_carry per layer
__device__ float g_h[L_ * BD_];             // carry h
__device__ float g_c[L_ * BD_];             // carry c
__device__ float g_gp[4 * B_ * 4 * D_];     // LSTM gate partials [ks][B][4096]
__device__ float g_xs[(long long)T_ * BD_]; // LSTM top-layer outputs (decoder input)

__device__ __forceinline__ float sigm(float x) { return 1.f / (1.f + expf(-x)); }
__device__ __forceinline__ float dot4(float4 a, float4 b) {
    return a.x*b.x + a.y*b.y + a.z*b.z + a.w*b.w;
}

// ---------------- init carry state ----------------
__global__ void k_init_state(const float* __restrict__ h0, const float* __restrict__ c0) {
    int i = blockIdx.x * blockDim.x + threadIdx.x;
    if (i < L_ * BD_) { g_h[i] = h0[i]; g_c[i] = c0[i]; }
}

// ================= batched-B GEMM tile: C[32, 64] over one K-chunk =========
// smem rows padded to 44 floats: stride 44 -> bank step 12 per 4-row group,
// LDS.128 conflict-free across the 8-thread phase; 44*4=176 keeps 16B align.
__device__ __forceinline__ void bg_mm(const float (&As)[32][44], const float (&Ws)[64][44],
                                      float (&acc)[4][4], int b0, int o0) {
#pragma unroll
    for (int kk = 0; kk < 8; kk++) {
        float4 a[4], w[4];
#pragma unroll
        for (int i = 0; i < 4; i++) a[i] = *(const float4*)&As[b0 + i][kk * 4];
#pragma unroll
        for (int j = 0; j < 4; j++) w[j] = *(const float4*)&Ws[o0 + j][kk * 4];
#pragma unroll
        for (int i = 0; i < 4; i++)
#pragma unroll
            for (int j = 0; j < 4; j++) acc[i][j] += dot4(a[i], w[j]);
    }
}

// ---------------- tiled SGEMM (decoder + cache init): C[M,N]=A@W^T+b -------
// asel: 1 -> A = g_xs ; csel: 0 -> g_Kc, 1 -> g_Vc, 2 -> Cext
__global__ __launch_bounds__(256, 2)
void k_gemm(const float* __restrict__ Aext, const float* __restrict__ W,
            const float* __restrict__ bias, float* Cext,
            int M, int N, int K, int asel, int csel) {
    const float* A = (asel == 1) ? (const float*)g_xs : Aext;
    float* C = (csel == 0) ? g_Kc : (csel == 1) ? g_Vc : Cext;

    __shared__ __align__(16) float As[8][128];
    __shared__ __align__(16) float Bs[8][128];

    int m0 = blockIdx.x * 128;
    int n0 = blockIdx.y * 128;
    int tid = threadIdx.x;
    int tr = tid / 16, tc = tid % 16;
    int lr = tid / 2;            // 0..127
    int lk = (tid % 2) * 4;      // 0 or 4

    float acc[8][8];
#pragma unroll
    for (int i = 0; i < 8; i++)
#pragma unroll
        for (int j = 0; j < 8; j++) acc[i][j] = 0.f;

    for (int k0 = 0; k0 < K; k0 += 8) {
        float4 av = make_float4(0,0,0,0), bv = make_float4(0,0,0,0);
        if (m0 + lr < M) av = *(const float4*)&A[(size_t)(m0 + lr) * K + k0 + lk];
        if (n0 + lr < N) bv = *(const float4*)&W[(size_t)(n0 + lr) * K + k0 + lk];
        __syncthreads();
        As[lk+0][lr] = av.x; As[lk+1][lr] = av.y; As[lk+2][lr] = av.z; As[lk+3][lr] = av.w;
        Bs[lk+0][lr] = bv.x; Bs[lk+1][lr] = bv.y; Bs[lk+2][lr] = bv.z; Bs[lk+3][lr] = bv.w;
        __syncthreads();
#pragma unroll
        for (int k = 0; k < 8; k++) {
            float af[8], bf[8];
            *(float4*)&af[0] = *(const float4*)&As[k][tr * 4];
            *(float4*)&af[4] = *(const float4*)&As[k][64 + tr * 4];
            *(float4*)&bf[0] = *(const float4*)&Bs[k][tc * 4];
            *(float4*)&bf[4] = *(const float4*)&Bs[k][64 + tc * 4];
#pragma unroll
            for (int i = 0; i < 8; i++)
#pragma unroll
                for (int j = 0; j < 8; j++) acc[i][j] += af[i] * bf[j];
        }
    }
    int rb[2] = { m0 + tr * 4, m0 + 64 + tr * 4 };
    int cb[2] = { n0 + tc * 4, n0 + 64 + tc * 4 };
#pragma unroll
    for (int ih = 0; ih < 2; ih++)
#pragma unroll
        for (int i = 0; i < 4; i++) {
            int m = rb[ih] + i;
            if (m >= M) continue;
#pragma unroll
            for (int jh = 0; jh < 2; jh++)
#pragma unroll
                for (int j = 0; j < 4; j++) {
                    int n = cb[jh] + j;
                    if (n < N) C[(size_t)m * N + n] = acc[ih*4+i][jh*4+j] + bias[n];
                }
        }
}

// ---------------- embed + LayerNorm ---------------- grid 32, 256 threads
__global__ void k_embed_ln(const int* __restrict__ tokens, const float* __restrict__ emb,
                           const float* __restrict__ lng, const float* __restrict__ lnb, int t) {
    __shared__ __align__(16) float esh[D_];
    __shared__ float rs[8], rs2[8];
    int b = blockIdx.x, tid = threadIdx.x;
    int tok = tokens[t * B_ + b];
    const float* erow = emb + (size_t)tok * D_;
    float s = 0.f, s2 = 0.f;
    for (int i = tid; i < D_; i += 256) { float v = erow[i]; esh[i] = v; s += v; s2 += v*v; }
#pragma unroll
    for (int o = 16; o; o >>= 1) { s += __shfl_xor_sync(~0u, s, o); s2 += __shfl_xor_sync(~0u, s2, o); }
    if ((tid & 31) == 0) { rs[tid >> 5] = s; rs2[tid >> 5] = s2; }
    __syncthreads();
    if (tid == 0) {
        float a = 0.f, c = 0.f;
        for (int w = 0; w < 8; w++) { a += rs[w]; c += rs2[w]; }
        rs[0] = a; rs2[0] = c;
    }
    __syncthreads();
    float mu  = rs[0] / D_;
    float var = (rs2[0] - (float)D_ * mu * mu) / (float)(D_ - 1);
    float inv = 1.f / (sqrtf(fmaxf(var, 0.f)) + EPS_);
    for (int i = tid; i < D_; i += 256) {
        float e = esh[i];
        g_e[b * D_ + i]  = e;
        g_ln[b * D_ + i] = lng[i] * (e - mu) * inv + lnb[i];
    }
}

// ---------------- fused q/k/v projection ---------------- grid 48, 128 thr
// seg 0: q = ln @ Wq^T + bq           -> g_q
// seg 1: k = h_new(t-1) @ Wk^T + bk   -> cache slot (t-1)%35   (skip at t=0)
// seg 2: v likewise                   -> g_Vc
__global__ __launch_bounds__(128) void k_proj(
        const float* __restrict__ Wq, const float* __restrict__ bq,
        const float* __restrict__ Wk, const float* __restrict__ bk,
        const float* __restrict__ Wv, const float* __restrict__ bv, int t) {
    int seg = blockIdx.x >> 4;
    if (t == 0 && seg) return;
    int n0 = (blockIdx.x & 15) * 64;
    const float* A; const float* W; const float* bias; float* C;
    if (seg == 0) { A = g_ln; W = Wq; bias = bq; C = g_q; }
    else {
        int slot = (t - 1) % MEM_;
        A = g_h;   // layer0 h_new from step t-1
        if (seg == 1) { W = Wk; bias = bk; C = g_Kc + (size_t)slot * BD_; }
        else          { W = Wv; bias = bv; C = g_Vc + (size_t)slot * BD_; }
    }
    __shared__ __align__(16) float As[32][44];
    __shared__ __align__(16) float Ws[64][44];
    int tid = threadIdx.x;
    float acc[4][4] = {};
    for (int kc = 0; kc < D_; kc += 32) {
        __syncthreads();
#pragma unroll
        for (int i = 0; i < 2; i++) {
            int idx = i * 128 + tid, row = idx >> 3, c4 = (idx & 7) * 4;
            *(float4*)&As[row][c4] = *(const float4*)&A[(size_t)row * D_ + kc + c4];
        }
#pragma unroll
        for (int i = 0; i < 4; i++) {
            int idx = i * 128 + tid, row = idx >> 3, c4 = (idx & 7) * 4;
            *(float4*)&Ws[row][c4] = *(const float4*)&W[(size_t)(n0 + row) * D_ + kc + c4];
        }
        __syncthreads();
        bg_mm(As, Ws, acc, (tid >> 4) * 4, (tid & 15) * 4);
    }
    int b0 = (tid >> 4) * 4, o0 = (tid & 15) * 4;
    float4 bi = *(const float4*)&bias[n0 + o0];
#pragma unroll
    for (int i = 0; i < 4; i++) {
        float4 v = make_float4(acc[i][0] + bi.x, acc[i][1] + bi.y,
                               acc[i][2] + bi.z, acc[i][3] + bi.w);
        *(float4*)&C[(size_t)(b0 + i) * D_ + n0 + o0] = v;
    }
}

// ---------------- batched attention scores ---------------- grid (18, 2), 128 thr
// scores[(h*32+b)][m] = (q[b, h*512:] . Kc[m, h*512:]) * SCALE
__global__ __launch_bounds__(128) void k_scores2() {
    int h = blockIdx.y;
    int n0 = blockIdx.x * 64;           // m tile
    __shared__ __align__(16) float As[32][44];
    __shared__ __align__(16) float Ws[64][44];
    int tid = threadIdx.x;
    float acc[4][4] = {};
    for (int kc = 0; kc < DK_; kc += 32) {
        __syncthreads();
#pragma unroll
        for (int i = 0; i < 2; i++) {
            int idx = i * 128 + tid, row = idx >> 3, c4 = (idx & 7) * 4;
            *(float4*)&As[row][c4] = *(const float4*)&g_q[(size_t)row * D_ + h * DK_ + kc + c4];
        }
#pragma unroll
        for (int i = 0; i < 4; i++) {
            int idx = i * 128 + tid, row = idx >> 3, c4 = (idx & 7) * 4;
            int m = n0 + row;
            float4 v = make_float4(0,0,0,0);
            if (m < MB_) v = *(const float4*)&g_Kc[(size_t)m * D_ + h * DK_ + kc + c4];
            *(float4*)&Ws[row][c4] = v;
        }
        __syncthreads();
        bg_mm(As, Ws, acc, (tid >> 4) * 4, (tid & 15) * 4);
    }
    int b0 = (tid >> 4) * 4, o0 = (tid & 15) * 4;
    int m = n0 + o0;
    if (m < MB_) {
        float* base = g_scores + (size_t)(h * B_) * MB_;
#pragma unroll
        for (int i = 0; i < 4; i++) {
            float4 v = make_float4(acc[i][0]*SCALE_, acc[i][1]*SCALE_,
                                   acc[i][2]*SCALE_, acc[i][3]*SCALE_);
            *(float4*)&base[(size_t)(b0 + i) * MB_ + m] = v;
        }
    }
}

// ---------------- softmax over m ---------------- grid 64, 256 threads
__global__ void k_softmax() {
    int hb = blockIdx.x, tid = threadIdx.x;
    float* row = g_scores + (size_t)hb * MB_;
    __shared__ float red[8];
    float mx = -1e30f;
    for (int i = tid; i < MB_; i += 256) mx = fmaxf(mx, row[i]);
#pragma unroll
    for (int o = 16; o; o >>= 1) mx = fmaxf(mx, __shfl_xor_sync(~0u, mx, o));
    if ((tid & 31) == 0) red[tid >> 5] = mx;
    __syncthreads();
    if (tid == 0) { float v = red[0]; for (int w = 1; w < 8; w++) v = fmaxf(v, red[w]); red[0] = v; }
    __syncthreads();
    mx = red[0];
    __syncthreads();
    float s = 0.f;
    for (int i = tid; i < MB_; i += 256) { float e = expf(row[i] - mx); row[i] = e; s += e; }
#pragma unroll
    for (int o = 16; o; o >>= 1) s += __shfl_xor_sync(~0u, s, o);
    if ((tid & 31) == 0) red[tid >> 5] = s;
    __syncthreads();
    if (tid == 0) { float v = 0.f; for (int w = 0; w < 8; w++) v += red[w]; red[0] = v; }
    __syncthreads();
    float inv = 1.f / red[0];
    for (int i = tid; i < MB_; i += 256) row[i] *= inv;
}

// ---------------- AV partials ---------------- grid (8, GAV_), 128 threads
__global__ void k_av() {
    __shared__ __align__(16) float sw[MTILE_][B_];
    int tid = threadIdx.x;
    int d = blockIdx.x * 128 + tid;
    int h = d >> 9;
    int m0 = blockIdx.y * MTILE_;
    for (int idx = tid; idx < MTILE_ * B_; idx += 128) {
        int mm = idx >> 5, bb = idx & 31;
        sw[mm][bb] = g_scores[(size_t)(h * B_ + bb) * MB_ + m0 + mm];
    }
    __syncthreads();
    float acc[B_];
#pragma unroll
    for (int i = 0; i < B_; i++) acc[i] = 0.f;
#pragma unroll 4
    for (int mm = 0; mm < MTILE_; mm++) {
        float v = g_Vc[(size_t)(m0 + mm) * D_ + d];
        const float4* w4 = (const float4*)sw[mm];
#pragma unroll
        for (int q = 0; q < 8; q++) {
            float4 w = w4[q];
            acc[q*4+0] += w.x * v; acc[q*4+1] += w.y * v;
            acc[q*4+2] += w.z * v; acc[q*4+3] += w.w * v;
        }
    }
    float* dst = g_attp + (size_t)blockIdx.y * BD_;
#pragma unroll
    for (int bb = 0; bb < B_; bb++) dst[bb * D_ + d] = acc[bb];
}

// ---------------- batched O-proj + residuals + hsum ---------------- grid 16, 128 thr
__global__ __launch_bounds__(128) void k_oproj(const float* __restrict__ Wo,
                                               const float* __restrict__ bo) {
    int n0 = blockIdx.x * 64;
    __shared__ __align__(16) float As[32][44];
    __shared__ __align__(16) float Ws[64][44];
    int tid = threadIdx.x;
    float acc[4][4] = {};
    for (int kc = 0; kc < D_; kc += 32) {
        __syncthreads();
#pragma unroll
        for (int i = 0; i < 2; i++) {
            int idx = i * 128 + tid, row = idx >> 3, c4 = (idx & 7) * 4;
            size_t off = (size_t)row * D_ + kc + c4;
            float4 s = *(const float4*)&g_attp[off];
#pragma unroll
            for (int g = 1; g < GAV_; g++) {
                float4 p = *(const float4*)&g_attp[(size_t)g * BD_ + off];
                s.x += p.x; s.y += p.y; s.z += p.z; s.w += p.w;
            }
            *(float4*)&As[row][c4] = s;
        }
#pragma unroll
        for (int i = 0; i < 4; i++) {
            int idx = i * 128 + tid, row = idx >> 3, c4 = (idx & 7) * 4;
            *(float4*)&Ws[row][c4] = *(const float4*)&Wo[(size_t)(n0 + row) * D_ + kc + c4];
        }
        __syncthreads();
        bg_mm(As, Ws, acc, (tid >> 4) * 4, (tid & 15) * 4);
    }
    int b0 = (tid >> 4) * 4, o0 = (tid & 15) * 4;
    int n = n0 + o0;
    float4 bi = *(const float4*)&bo[n];
#pragma unroll
    for (int i = 0; i < 4; i++) {
        size_t bd = (size_t)(b0 + i) * D_ + n;
        float4 e4 = *(const float4*)&g_e[bd];
        float4 h0 = *(const float4*)&g_h[bd];
        float4 h1 = *(const float4*)&g_h[BD_ + bd];
        float4 va = make_float4(acc[i][0] + bi.x + e4.x, acc[i][1] + bi.y + e4.y,
                                acc[i][2] + bi.z + e4.z, acc[i][3] + bi.w + e4.w);
        *(float4*)&g_hsum[bd]        = make_float4(va.x + h0.x, va.y + h0.y, va.z + h0.z, va.w + h0.w);
        *(float4*)&g_hsum[BD_ + bd]  = make_float4(va.x + h1.x, va.y + h1.y, va.z + h1.z, va.w + h1.w);
    }
}

// ---------------- LSTM gates GEMM (K-split x4) ---------------- grid (64,4), 128 thr
// partial[ks][b][n] = A_ks[b,:512] @ W_ks[n,:512]^T
__global__ __launch_bounds__(128) void k_lstm_gemm(const float* __restrict__ Wih,
                                                   const float* __restrict__ Whh, int l) {
    int n0 = blockIdx.x * 64;            // within 4096
    int ks = blockIdx.y;                 // 0,1: x via Wih ; 2,3: hsum via Whh
    const float* A = (ks < 2) ? ((l == 0) ? g_e : g_h) : (g_hsum + (size_t)l * BD_);
    int acol = (ks & 1) * 512;
    const float* W = (ks < 2) ? Wih : Whh;
    size_t wbase = ((size_t)l * 4 * D_ + n0) * D_ + acol;

    __shared__ __align__(16) float As[32][44];
    __shared__ __align__(16) float Ws[64][44];
    int tid = threadIdx.x;
    float acc[4][4] = {};
    for (int kc = 0; kc < 512; kc += 32) {
        __syncthreads();
#pragma unroll
        for (int i = 0; i < 2; i++) {
            int idx = i * 128 + tid, row = idx >> 3, c4 = (idx & 7) * 4;
            *(float4*)&As[row][c4] = *(const float4*)&A[(size_t)row * D_ + acol + kc + c4];
        }
#pragma unroll
        for (int i = 0; i < 4; i++) {
            int idx = i * 128 + tid, row = idx >> 3, c4 = (idx & 7) * 4;
            *(float4*)&Ws[row][c4] = *(const float4*)&W[wbase + (size_t)row * D_ + kc + c4];
        }
        __syncthreads();
        bg_mm(As, Ws, acc, (tid >> 4) * 4, (tid & 15) * 4);
    }
    int b0 = (tid >> 4) * 4, o0 = (tid & 15) * 4;
    float* dst = g_gp + (size_t)ks * B_ * 4 * D_;
#pragma unroll
    for (int i = 0; i < 4; i++) {
        float4 v = make_float4(acc[i][0], acc[i][1], acc[i][2], acc[i][3]);
        *(float4*)&dst[(size_t)(b0 + i) * 4 * D_ + n0 + o0] = v;
    }
}

// ---------------- LSTM elementwise ---------------- grid 128, 256 thr
__global__ void k_lstm_elt(const float* __restrict__ bih, const float* __restrict__ bhh,
                           int l, int t, float* __restrict__ out, int full) {
    int idx = blockIdx.x * 256 + threadIdx.x;   // 0..32767 = b*1024 + o
    int b = idx >> 10, o = idx & 1023;
    float gt[4];
#pragma unroll
    for (int g = 0; g < 4; g++) {
        int n = g * D_ + o;
        float v = bih[l * 4 * D_ + n] + bhh[l * 4 * D_ + n];
#pragma unroll
        for (int ks = 0; ks < 4; ks++)
            v += g_gp[(size_t)ks * B_ * 4 * D_ + (size_t)b * 4 * D_ + n];
        gt[g] = v;
    }
    float c_old = g_c[l * BD_ + idx];
    float cn = sigm(gt[1]) * c_old + sigm(gt[0]) * tanhf(gt[2]);
    float hn = sigm(gt[3]) * tanhf(cn);
    g_c[l * BD_ + idx] = cn;
    g_h[l * BD_ + idx] = hn;
    if (l == L_ - 1) g_xs[(size_t)t * BD_ + idx] = hn;
    if (full && t >= T_ - MEM_) {
        long long j = t - (T_ - MEM_);
        out[OFF_HM + (((long long)l * MEM_ + j) * B_ + b) * D_ + o] = hn;
        out[OFF_CM + (((long long)l * MEM_ + j) * B_ + b) * D_ + o] = cn;
    }
}

// ---------------- final h,c copy ----------------
__global__ void k_copy_hc(float* __restrict__ out) {
    int i = blockIdx.x * blockDim.x + threadIdx.x;
    if (i < L_ * BD_) { out[OFF_H + i] = g_h[i]; out[OFF_C + i] = g_c[i]; }
}

// ---------------- host launch ----------------
extern "C" void kernel_launch(void* const* d_in, const int* in_sizes, int n_in,
                              void* d_out, int out_size) {
    const int*   tokens = (const int*)  d_in[0];
    const float* emb    = (const float*)d_in[1];
    const float* ln_g   = (const float*)d_in[2];
    const float* ln_b   = (const float*)d_in[3];
    const float* Wq     = (const float*)d_in[4];
    const float* bq     = (const float*)d_in[5];
    const float* Wk     = (const float*)d_in[6];
    const float* bk     = (const float*)d_in[7];
    const float* Wv     = (const float*)d_in[8];
    const float* bv     = (const float*)d_in[9];
    const float* Wo     = (const float*)d_in[10];
    const float* bo     = (const float*)d_in[11];
    const float* W_ih   = (const float*)d_in[12];
    const float* b_ih   = (const float*)d_in[13];
    const float* W_hh   = (const float*)d_in[14];
    const float* b_hh   = (const float*)d_in[15];
    const float* dec_W  = (const float*)d_in[16];
    const float* dec_b  = (const float*)d_in[17];
    const float* h0     = (const float*)d_in[18];
    const float* c0     = (const float*)d_in[19];
    const float* H0     = (const float*)d_in[20];
    float* out = (float*)d_out;
    int full = (out_size >= (int)TOTAL_OUT) ? 1 : 0;

    k_init_state<<<(L_ * BD_ + 255) / 256, 256>>>(h0, c0);

    // K/V cache init from H0[0]  (M=1120, N=1024, K=1024)
    dim3 gi((MB_ + 127) / 128, D_ / 128);
    k_gemm<<<gi, 256>>>(H0, Wk, bk, nullptr, MB_, D_, D_, 0, 0);
    k_gemm<<<gi, 256>>>(H0, Wv, bv, nullptr, MB_, D_, D_, 0, 1);

    for (int t = 0; t < T_; t++) {
        k_embed_ln<<<B_, 256>>>(tokens, emb, ln_g, ln_b, t);
        k_proj<<<48, 128>>>(Wq, bq, Wk, bk, Wv, bv, t);
        k_scores2<<<dim3(18, 2), 128>>>();
        k_softmax<<<64, 256>>>();
        k_av<<<dim3(8, GAV_), 128>>>();
        k_oproj<<<16, 128>>>(Wo, bo);
        for (int l = 0; l < L_; l++) {
            k_lstm_gemm<<<dim3(64, 4), 128>>>(W_ih, W_hh, l);
            k_lstm_elt<<<128, 256>>>(b_ih, b_hh, l, t, out, full);
        }
    }

    if (full) k_copy_hc<<<(L_ * BD_ + 255) / 256, 256>>>(out);

    // decoder: [T*B, D] @ dec_W^T + dec_b -> decoded at out offset 0
    dim3 gd((T_ * B_) / 128, NTOK_ / 128);
    k_gemm<<<gd, 256>>>(nullptr, dec_W, dec_b, out, T_ * B_, NTOK_, D_, 1, 2);
}

// round 8
// speedup vs baseline: 3.2048x; 1.5671x over previous
#include <cuda_runtime.h>
#include <math.h>
#include <stdint.h>

// ---------------- problem constants ----------------
constexpr int T_    = 64;
constexpr int B_    = 32;
constexpr int D_    = 1024;
constexpr int L_    = 2;
constexpr int MEM_  = 35;
constexpr int NTOK_ = 32000;
constexpr int DK_   = 512;         // D / HEADS
constexpr int MB_   = MEM_ * B_;   // 1120
constexpr int BD_   = B_ * D_;     // 32768
constexpr float EPS_   = 1e-6f;
constexpr float SCALE_ = 0.04419417382415922f;  // 1/sqrt(512)

constexpr int NB_   = 296;         // persistent grid (co-resident: occ>=4 forced)
constexpr int GAV_  = 10;
constexpr int MTILE_ = 112;        // 1120 / 10

// output layout (floats): decoded, h, c, H, C
constexpr long long OFF_DEC = 0;
constexpr long long SZ_DEC  = (long long)T_ * B_ * NTOK_;
constexpr long long OFF_H   = OFF_DEC + SZ_DEC;
constexpr long long SZ_HC   = (long long)L_ * B_ * D_;
constexpr long long OFF_C   = OFF_H + SZ_HC;
constexpr long long OFF_HM  = OFF_C + SZ_HC;
constexpr long long SZ_HM   = (long long)L_ * MEM_ * B_ * D_;
constexpr long long OFF_CM  = OFF_HM + SZ_HM;
constexpr long long TOTAL_OUT = OFF_CM + SZ_HM;

// ---------------- device scratch (static; no allocation) ----------------
__device__ float g_e[BD_];
__device__ float g_ln[BD_];
__device__ float g_q[BD_];
__device__ float g_Kc[MEM_ * BD_];
__device__ float g_Vc[MEM_ * BD_];
__device__ float g_sc[2 * B_ * MB_];        // [(h*32+b)][1120]
__device__ float g_attp[GAV_ * BD_];
__device__ float g_att[BD_];
__device__ float g_hsum[L_ * BD_];
__device__ float g_h[L_ * BD_];
__device__ float g_c[L_ * BD_];
__device__ float g_gates[B_ * 4 * D_];      // [b][4096] full gate preacts
__device__ float g_xs[(long long)T_ * BD_];

__device__ unsigned g_bcount = 0;
__device__ volatile unsigned g_bgen = 0;

__device__ __forceinline__ float sigm(float x) { return 1.f / (1.f + expf(-x)); }

// ---------------- global barrier (all NB_ blocks) ----------------
__device__ __forceinline__ void gbar() {
    __syncthreads();
    if (threadIdx.x == 0) {
        unsigned gen = g_bgen;
        __threadfence();                     // publish writes (+ L1 inval on sm_103a)
        if (atomicAdd(&g_bcount, 1u) == NB_ - 1) {
            g_bcount = 0;
            __threadfence();
            g_bgen = gen + 1;
        } else {
            while (g_bgen == gen) __nanosleep(40);
            __threadfence();                 // acquire + L1 inval
        }
    }
    __syncthreads();
}

// ---------------- 32b x 16n tile GEMM, full-K accumulate ----------------
// acc[i] += A[b0+i, :K] . W[o, :K]   (A rows stride lda, W rows stride ldw)
// 128 threads; sA = 32x44 floats, sW = 16x44 floats (conflict-free padding).
__device__ __forceinline__ void tile16(const float* __restrict__ A, int lda,
                                       const float* __restrict__ W, int ldw,
                                       int K, float* sA, float* sW, float acc[4]) {
    int tid = threadIdx.x;
    int c4  = (tid & 7) * 4;
    int ar0 = tid >> 3;             // 0..15
    int ar1 = 16 + ar0;             // 16..31
    int wr  = tid >> 3;             // 0..15
    const float* Ap0 = A + (size_t)ar0 * lda + c4;
    const float* Ap1 = A + (size_t)ar1 * lda + c4;
    const float* Wp  = W + (size_t)wr  * ldw + c4;
    int o  = tid & 15;
    int b0 = (tid >> 4) * 4;
    float4 a0 = *(const float4*)Ap0;
    float4 a1 = *(const float4*)Ap1;
    float4 w0 = *(const float4*)Wp;
    for (int kc = 0; kc < K; kc += 32) {
        __syncthreads();
        *(float4*)&sA[ar0 * 44 + c4] = a0;
        *(float4*)&sA[ar1 * 44 + c4] = a1;
        *(float4*)&sW[wr  * 44 + c4] = w0;
        __syncthreads();
        if (kc + 32 < K) {                    // prefetch next chunk (overlaps FFMA)
            a0 = *(const float4*)(Ap0 + kc + 32);
            a1 = *(const float4*)(Ap1 + kc + 32);
            w0 = *(const float4*)(Wp  + kc + 32);
        }
#pragma unroll
        for (int kk = 0; kk < 8; kk++) {
            float4 w = *(const float4*)&sW[o * 44 + kk * 4];
#pragma unroll
            for (int i = 0; i < 4; i++) {
                float4 a = *(const float4*)&sA[(b0 + i) * 44 + kk * 4];
                acc[i] += a.x * w.x + a.y * w.y + a.z * w.z + a.w * w.w;
            }
        }
    }
}

// ---------------- init carry state ----------------
__global__ void k_init_state(const float* __restrict__ h0, const float* __restrict__ c0) {
    int i = blockIdx.x * blockDim.x + threadIdx.x;
    if (i < L_ * BD_) { g_h[i] = h0[i]; g_c[i] = c0[i]; }
}

// ---------------- tiled SGEMM (cache init + decoder) ----------------
__global__ __launch_bounds__(256, 2)
void k_gemm(const float* __restrict__ Aext, const float* __restrict__ W,
            const float* __restrict__ bias, float* Cext,
            int M, int N, int K, int asel, int csel) {
    const float* A = (asel == 1) ? (const float*)g_xs : Aext;
    float* C = (csel == 0) ? g_Kc : (csel == 1) ? g_Vc : Cext;

    __shared__ __align__(16) float As[8][128];
    __shared__ __align__(16) float Bs[8][128];

    int m0 = blockIdx.x * 128;
    int n0 = blockIdx.y * 128;
    int tid = threadIdx.x;
    int tr = tid / 16, tc = tid % 16;
    int lr = tid / 2;
    int lk = (tid % 2) * 4;

    float acc[8][8];
#pragma unroll
    for (int i = 0; i < 8; i++)
#pragma unroll
        for (int j = 0; j < 8; j++) acc[i][j] = 0.f;

    for (int k0 = 0; k0 < K; k0 += 8) {
        float4 av = make_float4(0,0,0,0), bv = make_float4(0,0,0,0);
        if (m0 + lr < M) av = *(const float4*)&A[(size_t)(m0 + lr) * K + k0 + lk];
        if (n0 + lr < N) bv = *(const float4*)&W[(size_t)(n0 + lr) * K + k0 + lk];
        __syncthreads();
        As[lk+0][lr] = av.x; As[lk+1][lr] = av.y; As[lk+2][lr] = av.z; As[lk+3][lr] = av.w;
        Bs[lk+0][lr] = bv.x; Bs[lk+1][lr] = bv.y; Bs[lk+2][lr] = bv.z; Bs[lk+3][lr] = bv.w;
        __syncthreads();
#pragma unroll
        for (int k = 0; k < 8; k++) {
            float af[8], bf[8];
            *(float4*)&af[0] = *(const float4*)&As[k][tr * 4];
            *(float4*)&af[4] = *(const float4*)&As[k][64 + tr * 4];
            *(float4*)&bf[0] = *(const float4*)&Bs[k][tc * 4];
            *(float4*)&bf[4] = *(const float4*)&Bs[k][64 + tc * 4];
#pragma unroll
            for (int i = 0; i < 8; i++)
#pragma unroll
                for (int j = 0; j < 8; j++) acc[i][j] += af[i] * bf[j];
        }
    }
    int rb[2] = { m0 + tr * 4, m0 + 64 + tr * 4 };
    int cb[2] = { n0 + tc * 4, n0 + 64 + tc * 4 };
#pragma unroll
    for (int ih = 0; ih < 2; ih++)
#pragma unroll
        for (int i = 0; i < 4; i++) {
            int m = rb[ih] + i;
            if (m >= M) continue;
#pragma unroll
            for (int jh = 0; jh < 2; jh++)
#pragma unroll
                for (int j = 0; j < 4; j++) {
                    int n = cb[jh] + j;
                    if (n < N) C[(size_t)m * N + n] = acc[ih*4+i][jh*4+j] + bias[n];
                }
        }
}

// ---------------- persistent step-loop kernel ----------------
__global__ __launch_bounds__(128, 4)
void k_steps(const int* __restrict__ tokens, const float* __restrict__ emb,
             const float* __restrict__ lng, const float* __restrict__ lnb,
             const float* __restrict__ Wq, const float* __restrict__ bq,
             const float* __restrict__ Wk, const float* __restrict__ bk,
             const float* __restrict__ Wv, const float* __restrict__ bv,
             const float* __restrict__ Wo, const float* __restrict__ bo,
             const float* __restrict__ Wih, const float* __restrict__ bih,
             const float* __restrict__ Whh, const float* __restrict__ bhh,
             float* __restrict__ out, int full) {
    __shared__ __align__(16) float sbuf[3584];    // 14 KB: tiles or AV staging
    __shared__ float red1[4], red2[4];
    float* sA = sbuf;               // 32*44 = 1408
    float* sW = sbuf + 1408;        // 16*44 = 704
    int bid = blockIdx.x, tid = threadIdx.x;
    int wid = tid >> 5, lid = tid & 31;

    for (int t = 0; t < T_; t++) {
        // ---- Ph0: embed + LayerNorm (32 tasks) ----
        for (int task = bid; task < B_; task += NB_) {
            int tok = tokens[t * B_ + task];
            const float* er = emb + (size_t)tok * D_;
            float4 v0 = *(const float4*)(er + tid * 8);
            float4 v1 = *(const float4*)(er + tid * 8 + 4);
            float s  = v0.x+v0.y+v0.z+v0.w + v1.x+v1.y+v1.z+v1.w;
            float s2 = v0.x*v0.x+v0.y*v0.y+v0.z*v0.z+v0.w*v0.w
                     + v1.x*v1.x+v1.y*v1.y+v1.z*v1.z+v1.w*v1.w;
#pragma unroll
            for (int o = 16; o; o >>= 1) {
                s  += __shfl_xor_sync(~0u, s,  o);
                s2 += __shfl_xor_sync(~0u, s2, o);
            }
            if (lid == 0) { red1[wid] = s; red2[wid] = s2; }
            __syncthreads();
            float S = red1[0]+red1[1]+red1[2]+red1[3];
            float S2 = red2[0]+red2[1]+red2[2]+red2[3];
            float mu  = S / D_;
            float var = (S2 - (float)D_ * mu * mu) / (float)(D_ - 1);
            float inv = 1.f / (sqrtf(fmaxf(var, 0.f)) + EPS_);
            float4 g0 = *(const float4*)(lng + tid * 8);
            float4 g1 = *(const float4*)(lng + tid * 8 + 4);
            float4 b0 = *(const float4*)(lnb + tid * 8);
            float4 b1 = *(const float4*)(lnb + tid * 8 + 4);
            size_t base = (size_t)task * D_ + tid * 8;
            *(float4*)&g_e[base]     = v0;
            *(float4*)&g_e[base + 4] = v1;
            float4 n0 = make_float4(g0.x*(v0.x-mu)*inv + b0.x, g0.y*(v0.y-mu)*inv + b0.y,
                                    g0.z*(v0.z-mu)*inv + b0.z, g0.w*(v0.w-mu)*inv + b0.w);
            float4 n1 = make_float4(g1.x*(v1.x-mu)*inv + b1.x, g1.y*(v1.y-mu)*inv + b1.y,
                                    g1.z*(v1.z-mu)*inv + b1.z, g1.w*(v1.w-mu)*inv + b1.w);
            *(float4*)&g_ln[base]     = n0;
            *(float4*)&g_ln[base + 4] = n1;
        }
        gbar();

        // ---- Ph1: q projection (64 tasks, 16-n tiles, K=1024) ----
        for (int task = bid; task < 64; task += NB_) {
            int n0 = task * 16;
            float acc[4] = {};
            tile16(g_ln, D_, Wq + (size_t)n0 * D_, D_, D_, sA, sW, acc);
            int o = tid & 15, b0 = (tid >> 4) * 4;
            float bqv = bq[n0 + o];
#pragma unroll
            for (int i = 0; i < 4; i++)
                g_q[(size_t)(b0 + i) * D_ + n0 + o] = acc[i] + bqv;
        }
        gbar();

        // ---- Ph2: scores (140 tasks = 2 heads x 70 m-tiles, K=512) ----
        for (int task = bid; task < 140; task += NB_) {
            int h = task / 70, m0 = (task % 70) * 16;
            float acc[4] = {};
            tile16(g_q + h * DK_, D_, g_Kc + (size_t)m0 * D_ + h * DK_, D_, DK_, sA, sW, acc);
            int o = tid & 15, b0 = (tid >> 4) * 4;
#pragma unroll
            for (int i = 0; i < 4; i++)
                g_sc[(size_t)(h * B_ + b0 + i) * MB_ + m0 + o] = acc[i] * SCALE_;
        }
        gbar();

        // ---- Ph3: softmax (64 rows) ----
        for (int task = bid; task < 64; task += NB_) {
            float* row = g_sc + (size_t)task * MB_;
            float mx = -1e30f;
            for (int i = tid; i < MB_; i += 128) mx = fmaxf(mx, row[i]);
#pragma unroll
            for (int o = 16; o; o >>= 1) mx = fmaxf(mx, __shfl_xor_sync(~0u, mx, o));
            if (lid == 0) red1[wid] = mx;
            __syncthreads();
            mx = fmaxf(fmaxf(red1[0], red1[1]), fmaxf(red1[2], red1[3]));
            __syncthreads();
            float s = 0.f;
            for (int i = tid; i < MB_; i += 128) { float e = expf(row[i] - mx); row[i] = e; s += e; }
#pragma unroll
            for (int o = 16; o; o >>= 1) s += __shfl_xor_sync(~0u, s, o);
            if (lid == 0) red2[wid] = s;
            __syncthreads();
            float inv = 1.f / (red2[0]+red2[1]+red2[2]+red2[3]);
            for (int i = tid; i < MB_; i += 128) row[i] *= inv;
        }
        gbar();

        // ---- Ph4: AV partials (80 tasks) ----
        for (int task = bid; task < 8 * GAV_; task += NB_) {
            int gx = task & 7, gy = task >> 3;
            float (*sw)[B_] = (float (*)[B_])sbuf;   // 112 x 32
            int d = gx * 128 + tid;
            int h = d >> 9;
            int m0 = gy * MTILE_;
            for (int idx = tid; idx < MTILE_ * B_; idx += 128) {
                int mm = idx >> 5, bb = idx & 31;
                sw[mm][bb] = g_sc[(size_t)(h * B_ + bb) * MB_ + m0 + mm];
            }
            __syncthreads();
            float acc[B_];
#pragma unroll
            for (int i = 0; i < B_; i++) acc[i] = 0.f;
#pragma unroll 4
            for (int mm = 0; mm < MTILE_; mm++) {
                float v = g_Vc[(size_t)(m0 + mm) * D_ + d];
                const float4* w4 = (const float4*)sw[mm];
#pragma unroll
                for (int q = 0; q < 8; q++) {
                    float4 w = w4[q];
                    acc[q*4+0] += w.x * v; acc[q*4+1] += w.y * v;
                    acc[q*4+2] += w.z * v; acc[q*4+3] += w.w * v;
                }
            }
            float* dst = g_attp + (size_t)gy * BD_;
#pragma unroll
            for (int bb = 0; bb < B_; bb++) dst[bb * D_ + d] = acc[bb];
        }
        gbar();

        // ---- Ph5: reduce AV partials ----
        for (int i = bid * 128 + tid; i < BD_; i += NB_ * 128) {
            float s = g_attp[i];
#pragma unroll
            for (int g = 1; g < GAV_; g++) s += g_attp[(size_t)g * BD_ + i];
            g_att[i] = s;
        }
        gbar();

        // ---- Ph6: O-proj + residuals -> hsum (64 tasks) ----
        for (int task = bid; task < 64; task += NB_) {
            int n0 = task * 16;
            float acc[4] = {};
            tile16(g_att, D_, Wo + (size_t)n0 * D_, D_, D_, sA, sW, acc);
            int o = tid & 15, b0 = (tid >> 4) * 4;
            float bov = bo[n0 + o];
#pragma unroll
            for (int i = 0; i < 4; i++) {
                size_t idx = (size_t)(b0 + i) * D_ + n0 + o;
                float ha = acc[i] + bov + g_e[idx];
                g_hsum[idx]       = ha + g_h[idx];
                g_hsum[BD_ + idx] = ha + g_h[BD_ + idx];
            }
        }
        gbar();

        // ---- Ph7/Ph9: LSTM per layer (+ kv folded into layer-1 phase) ----
        for (int l = 0; l < L_; l++) {
            int ntasks = (l == 0) ? 256 : 256 + 128;
            for (int task = bid; task < ntasks; task += NB_) {
                if (task < 256) {
                    int n0 = task * 16;
                    float acc[4] = {};
                    const float* x = (l == 0) ? g_e : g_h;
                    tile16(x, D_, Wih + ((size_t)l * 4 * D_ + n0) * D_, D_, D_, sA, sW, acc);
                    tile16(g_hsum + (size_t)l * BD_, D_,
                           Whh + ((size_t)l * 4 * D_ + n0) * D_, D_, D_, sA, sW, acc);
                    int o = tid & 15, b0 = (tid >> 4) * 4;
#pragma unroll
                    for (int i = 0; i < 4; i++)
                        g_gates[(size_t)(b0 + i) * 4 * D_ + n0 + o] = acc[i];
                } else {
                    int tk = task - 256;          // only l==1: kv proj from h_l0(t)
                    int mat = tk >> 6, n0 = (tk & 63) * 16;
                    float acc[4] = {};
                    const float* W = mat ? Wv : Wk;
                    const float* bb = mat ? bv : bk;
                    tile16(g_h, D_, W + (size_t)n0 * D_, D_, D_, sA, sW, acc);
                    int slot = t % MEM_;
                    float* dst = (mat ? g_Vc : g_Kc) + (size_t)slot * BD_;
                    int o = tid & 15, b0 = (tid >> 4) * 4;
                    float bvv = bb[n0 + o];
#pragma unroll
                    for (int i = 0; i < 4; i++)
                        dst[(size_t)(b0 + i) * D_ + n0 + o] = acc[i] + bvv;
                }
            }
            gbar();

            // ---- Ph8/Ph10: elementwise gate math + state/output writes ----
            for (int i = bid * 128 + tid; i < BD_; i += NB_ * 128) {
                int b = i >> 10, o = i & 1023;
                size_t gb = (size_t)b * 4 * D_;
                int jb = l * 4 * D_;
                float ig = g_gates[gb + o]            + bih[jb + o]            + bhh[jb + o];
                float fg = g_gates[gb + D_ + o]       + bih[jb + D_ + o]       + bhh[jb + D_ + o];
                float gg = g_gates[gb + 2*D_ + o]     + bih[jb + 2*D_ + o]     + bhh[jb + 2*D_ + o];
                float og = g_gates[gb + 3*D_ + o]     + bih[jb + 3*D_ + o]     + bhh[jb + 3*D_ + o];
                float c_old = g_c[l * BD_ + i];
                float cn = sigm(fg) * c_old + sigm(ig) * tanhf(gg);
                float hn = sigm(og) * tanhf(cn);
                g_c[l * BD_ + i] = cn;
                g_h[l * BD_ + i] = hn;
                if (l == L_ - 1) g_xs[(size_t)t * BD_ + i] = hn;
                if (full && t >= T_ - MEM_) {
                    long long j = t - (T_ - MEM_);
                    out[OFF_HM + (((long long)l * MEM_ + j) * B_ + b) * D_ + o] = hn;
                    out[OFF_CM + (((long long)l * MEM_ + j) * B_ + b) * D_ + o] = cn;
                }
            }
            gbar();
        }
    }
}

// ---------------- final h,c copy ----------------
__global__ void k_copy_hc(float* __restrict__ out) {
    int i = blockIdx.x * blockDim.x + threadIdx.x;
    if (i < L_ * BD_) { out[OFF_H + i] = g_h[i]; out[OFF_C + i] = g_c[i]; }
}

// ---------------- host launch ----------------
extern "C" void kernel_launch(void* const* d_in, const int* in_sizes, int n_in,
                              void* d_out, int out_size) {
    const int*   tokens = (const int*)  d_in[0];
    const float* emb    = (const float*)d_in[1];
    const float* ln_g   = (const float*)d_in[2];
    const float* ln_b   = (const float*)d_in[3];
    const float* Wq     = (const float*)d_in[4];
    const float* bq     = (const float*)d_in[5];
    const float* Wk     = (const float*)d_in[6];
    const float* bk     = (const float*)d_in[7];
    const float* Wv     = (const float*)d_in[8];
    const float* bv     = (const float*)d_in[9];
    const float* Wo     = (const float*)d_in[10];
    const float* bo     = (const float*)d_in[11];
    const float* W_ih   = (const float*)d_in[12];
    const float* b_ih   = (const float*)d_in[13];
    const float* W_hh   = (const float*)d_in[14];
    const float* b_hh   = (const float*)d_in[15];
    const float* dec_W  = (const float*)d_in[16];
    const float* dec_b  = (const float*)d_in[17];
    const float* h0     = (const float*)d_in[18];
    const float* c0     = (const float*)d_in[19];
    const float* H0     = (const float*)d_in[20];
    float* out = (float*)d_out;
    int full = (out_size >= (int)TOTAL_OUT) ? 1 : 0;

    k_init_state<<<(L_ * BD_ + 255) / 256, 256>>>(h0, c0);

    // K/V cache init from H0[0]  (M=1120, N=1024, K=1024)
    dim3 gi((MB_ + 127) / 128, D_ / 128);
    k_gemm<<<gi, 256>>>(H0, Wk, bk, nullptr, MB_, D_, D_, 0, 0);
    k_gemm<<<gi, 256>>>(H0, Wv, bv, nullptr, MB_, D_, D_, 0, 1);

    // whole 64-step recurrence in one persistent kernel
    k_steps<<<NB_, 128>>>(tokens, emb, ln_g, ln_b, Wq, bq, Wk, bk, Wv, bv,
                          Wo, bo, W_ih, b_ih, W_hh, b_hh, out, full);

    if (full) k_copy_hc<<<(L_ * BD_ + 255) / 256, 256>>>(out);

    // decoder: [T*B, D] @ dec_W^T + dec_b
    dim3 gd((T_ * B_) / 128, NTOK_ / 128);
    k_gemm<<<gd, 256>>>(nullptr, dec_W, dec_b, out, T_ * B_, NTOK_, D_, 1, 2);
}